// round 14
// baseline (speedup 1.0000x reference)
#include <cuda_runtime.h>
#include <math.h>

#define HH 768
#define WW 768
#define LL 8
#define PP 36
#define NPIX (HH*WW)
#define CBLK 128
#define CPAD 37

#define C_SIGMAP (1.0f / 11.0f)   /* 1/(3+L) */
#define C_LMBDA  0.1f
#define C_NU     0.01f
#define C_TAUU   (1.0f / 6.0f)
#define C_TAUM   (1.0f / 11.0f)   /* 1/(2+PROJ/4) */

// ---- scratch (allocation-free rule: device globals) ----
__device__ float g_p1[NPIX * LL];
__device__ float g_p2[NPIX * LL];
__device__ float g_p3[NPIX * LL];
__device__ float g_mso1[NPIX * LL];   // level-sums of INPUT mu   (kernC -> kernA iter1)
__device__ float g_mso2[NPIX * LL];
__device__ float g_msp1[NPIX * LL];   // mso + tau*levelsum(proj s) (kernC -> kernB<true>)
__device__ float g_msp2[NPIX * LL];
__device__ float g_msn1[NPIX * LL];   // updated mu level-sums (kernB<true> -> kernA iter2)
__device__ float g_msn2[NPIX * LL];
__device__ float g_u [NPIX * LL];
__device__ float g_ub[NPIX * LL];

// K -> (k1,k2) for the upper-triangular combo ordering (k1 outer, k2 inner)
__device__ __host__ constexpr int kk1(int K) {
    int k1 = 0, r = K, c = LL;
    while (r >= c) { r -= c; k1++; c--; }
    return k1;
}
__device__ __host__ constexpr int kk2(int K) {
    int k1 = 0, r = K, c = LL;
    while (r >= c) { r -= c; k1++; c--; }
    return k1 + r;
}

__device__ __forceinline__ void ld8(const float* __restrict__ p, float* v) {
    float4 a = *(const float4*)p;
    float4 b = *(const float4*)(p + 4);
    v[0]=a.x; v[1]=a.y; v[2]=a.z; v[3]=a.w;
    v[4]=b.x; v[5]=b.y; v[6]=b.z; v[7]=b.w;
}
__device__ __forceinline__ void st8(float* __restrict__ p, const float* v) {
    *(float4*)p       = make_float4(v[0], v[1], v[2], v[3]);
    *(float4*)(p + 4) = make_float4(v[4], v[5], v[6], v[7]);
}

// transposed scatter of 9 float4s into a padded buffer
__device__ __forceinline__ void sts_padded(float* buf, const float4* q, int tid) {
    #pragma unroll
    for (int i = 0; i < 9; i++) {
        int flat = (i * CBLK + tid) * 4;
        float v[4] = {q[i].x, q[i].y, q[i].z, q[i].w};
        #pragma unroll
        for (int e = 0; e < 4; e++) {
            int fe = flat + e;
            buf[(fe / PP) * CPAD + (fe % PP)] = v[e];
        }
    }
}

// interval-difference reduce of one padded row -> level sums
__device__ __forceinline__ void reduce_row(const float* row, float* ms) {
    float d[LL + 1];
    #pragma unroll
    for (int z = 0; z <= LL; z++) d[z] = 0.0f;
    #pragma unroll
    for (int K = 0; K < PP; K++) {
        float v = row[K];
        d[kk1(K)] += v;  d[kk2(K) + 1] -= v;
    }
    float a = 0.0f;
    #pragma unroll
    for (int z = 0; z < LL; z++) { a += d[z]; ms[z] = a; }
}

// =====================================================================
// Kernel C: PP-field streaming, software-pipelined. Next stage's global
// loads are issued into registers BEFORE the current stage's barrier +
// smem reduce, keeping DRAM busy through the reduce phases.
// Emits: mso = level-sums of input mu
//        msp = mso + tau * level-sums(proj(s - mb))
// =====================================================================
__global__ __launch_bounds__(CBLK)
void kernC(const float* __restrict__ mu1i, const float* __restrict__ mu2i,
           const float* __restrict__ s1i,  const float* __restrict__ s2i,
           const float* __restrict__ mb1i, const float* __restrict__ mb2i,
           float* __restrict__ mso1, float* __restrict__ mso2,
           float* __restrict__ msp1, float* __restrict__ msp2)
{
    __shared__ float buf0[CBLK * CPAD];
    __shared__ float buf1[CBLK * CPAD];

    const int tid = threadIdx.x;
    const int pix = blockIdx.x * CBLK + tid;
    const size_t base = (size_t)blockIdx.x * CBLK * PP;

    const float4* gmu1 = (const float4*)(mu1i + base);
    const float4* gmu2 = (const float4*)(mu2i + base);
    const float4* gs1  = (const float4*)(s1i  + base);
    const float4* gs2  = (const float4*)(s2i  + base);
    const float4* gmb1 = (const float4*)(mb1i + base);
    const float4* gmb2 = (const float4*)(mb2i + base);

    // ---- stage 0: load mu1, stage into buf0 ----
    {
        float4 q[9];
        #pragma unroll
        for (int i = 0; i < 9; i++) q[i] = gmu1[i * CBLK + tid];
        sts_padded(buf0, q, tid);
    }

    // ---- prefetch mu2 into regs (in flight across reduce0) ----
    float4 pre[9];
    #pragma unroll
    for (int i = 0; i < 9; i++) pre[i] = gmu2[i * CBLK + tid];

    __syncthreads();

    // ---- reduce0: mu1 level sums ----
    float ms1[LL], ms2[LL];
    reduce_row(buf0 + tid * CPAD, ms1);
    st8(mso1 + pix * LL, ms1);

    __syncthreads();   // buf0 free; also buf1 ready to write

    // ---- stage 1: mu2 into buf1; prefetch a1 = s1 - mb1 ----
    sts_padded(buf1, pre, tid);
    #pragma unroll
    for (int i = 0; i < 9; i++) {
        float4 qs = gs1[i * CBLK + tid];
        float4 qm = gmb1[i * CBLK + tid];
        pre[i] = make_float4(qs.x - qm.x, qs.y - qm.y, qs.z - qm.z, qs.w - qm.w);
    }

    __syncthreads();

    // ---- reduce1: mu2 level sums ----
    reduce_row(buf1 + tid * CPAD, ms2);
    st8(mso2 + pix * LL, ms2);

    __syncthreads();   // buf1 free

    // ---- stage 2: a1 into buf0; prefetch a2 = s2 - mb2 ----
    sts_padded(buf0, pre, tid);
    #pragma unroll
    for (int i = 0; i < 9; i++) {
        float4 qs = gs2[i * CBLK + tid];
        float4 qm = gmb2[i * CBLK + tid];
        pre[i] = make_float4(qs.x - qm.x, qs.y - qm.y, qs.z - qm.z, qs.w - qm.w);
    }
    sts_padded(buf1, pre, tid);

    __syncthreads();

    // ---- reduce2: projected (a1, a2) level sums -> msp ----
    {
        float d1[LL + 1], d2[LL + 1];
        #pragma unroll
        for (int z = 0; z <= LL; z++) { d1[z] = 0.0f; d2[z] = 0.0f; }
        const float* rowA = buf0 + tid * CPAD;
        const float* rowB = buf1 + tid * CPAD;
        #pragma unroll
        for (int K = 0; K < PP; K++) {
            float a1 = rowA[K];
            float a2 = rowB[K];
            float nr = sqrtf(a1 * a1 + a2 * a2);
            if (nr > C_NU) { float rr = __fdividef(C_NU, nr); a1 *= rr; a2 *= rr; }
            d1[kk1(K)] += a1;  d1[kk2(K) + 1] -= a1;
            d2[kk1(K)] += a2;  d2[kk2(K) + 1] -= a2;
        }
        float a1 = 0.0f, a2 = 0.0f;
        float o1[LL], o2[LL];
        #pragma unroll
        for (int z = 0; z < LL; z++) {
            a1 += d1[z]; a2 += d2[z];
            o1[z] = ms1[z] + C_TAUM * a1;
            o2[z] = ms2[z] + C_TAUM * a2;
        }
        st8(msp1 + pix * LL, o1);
        st8(msp2 + pix * LL, o2);
    }
}

// =====================================================================
// Kernel A: parabola projection only; mu inputs are level-sums [LL].
// =====================================================================
__global__ __launch_bounds__(256)
void kernA(const float* __restrict__ ubar,
           const float* __restrict__ p1i, const float* __restrict__ p2i, const float* __restrict__ p3i,
           const float* __restrict__ ms1i, const float* __restrict__ ms2i,
           const float* __restrict__ f,
           float* __restrict__ p1o, float* __restrict__ p2o, float* __restrict__ p3o)
{
    int pix = blockIdx.x * blockDim.x + threadIdx.x;
    if (pix >= NPIX) return;
    int w = pix % WW;
    int h = pix / WW;

    float U1[LL], U2[LL], U3[LL];
    {
        float ub[LL];
        ld8(ubar + pix * LL, ub);
        if (h < HH - 1) {
            float nb[LL]; ld8(ubar + (pix + WW) * LL, nb);
            #pragma unroll
            for (int z = 0; z < LL; z++) U1[z] = nb[z] - ub[z];
        } else {
            #pragma unroll
            for (int z = 0; z < LL; z++) U1[z] = 0.0f;
        }
        if (w < WW - 1) {
            float nb[LL]; ld8(ubar + (pix + 1) * LL, nb);
            #pragma unroll
            for (int z = 0; z < LL; z++) U2[z] = nb[z] - ub[z];
        } else {
            #pragma unroll
            for (int z = 0; z < LL; z++) U2[z] = 0.0f;
        }
        #pragma unroll
        for (int z = 0; z < LL; z++) U3[z] = (z < LL - 1) ? (ub[z + 1] - ub[z]) : 0.0f;
    }

    {
        float ms[LL], pv[LL];
        ld8(ms1i + pix * LL, ms);
        ld8(p1i + pix * LL, pv);
        #pragma unroll
        for (int z = 0; z < LL; z++) U1[z] = pv[z] + C_SIGMAP * (U1[z] + ms[z]);
        ld8(ms2i + pix * LL, ms);
        ld8(p2i + pix * LL, pv);
        #pragma unroll
        for (int z = 0; z < LL; z++) U2[z] = pv[z] + C_SIGMAP * (U2[z] + ms[z]);
        ld8(p3i + pix * LL, pv);
        #pragma unroll
        for (int z = 0; z < LL; z++) U3[z] = pv[z] + C_SIGMAP * U3[z];
    }

    float fv = __ldg(f + pix);

    #pragma unroll
    for (int z = 0; z < LL; z++) {
        float t    = (float)(z + 1) * (1.0f / (float)LL) - fv;
        float quad = C_LMBDA * t * t;
        float n2   = U1[z] * U1[z] + U2[z] * U2[z];
        float B    = 0.25f * n2 - quad;
        if (U3[z] < B) {
            float y   = U3[z] + quad;
            float nrm = sqrtf(n2);
            float a   = 0.5f * nrm;
            float b   = (2.0f / 3.0f) * (1.0f - 0.5f * y);
            float sb  = sqrtf(fmaxf(-b, 0.0f));
            float sb3 = sb * sb * sb;
            float d   = (b < 0.0f) ? (a - sb3) * (a + sb3) : fmaf(b * b, b, a * a);
            float v;
            if (d < 0.0f) {
                float ca = fminf(fmaxf(__fdividef(a, sb3), -1.0f), 1.0f);
                v = 2.0f * sb * __cosf(acosf(ca) * (1.0f / 3.0f));
            } else {
                float x  = a + sqrtf(d);
                float c  = (x > 0.0f) ? __powf(x, 1.0f / 3.0f) : 0.0f;
                v = (c == 0.0f) ? 0.0f : (c - __fdividef(b, c));
            }
            float r1, r2;
            if (nrm == 0.0f) { r1 = 0.0f; r2 = 0.0f; }
            else {
                float s = __fdividef(2.0f * v, nrm);
                r1 = s * U1[z]; r2 = s * U2[z];
            }
            U1[z] = r1;
            U2[z] = r2;
            U3[z] = 0.25f * (r1 * r1 + r2 * r2) - quad;
        }
    }
    st8(p1o + pix * LL, U1);
    st8(p2o + pix * LL, U2);
    st8(p3o + pix * LL, U3);
}

// =====================================================================
// Kernel B: clipping. FULL additionally finishes the mu update:
//   msn[z] = msp[z] - tau * TS[z]
// =====================================================================
template <bool FULL>
__global__ __launch_bounds__(256)
void kernB(const float* __restrict__ ui,
           const float* __restrict__ p1, const float* __restrict__ p2, const float* __restrict__ p3,
           const float* __restrict__ msp1, const float* __restrict__ msp2,
           float* __restrict__ uo, float* __restrict__ ubo,
           float* __restrict__ msn1, float* __restrict__ msn2)
{
    int pix = blockIdx.x * blockDim.x + threadIdx.x;
    if (pix >= NPIX) return;
    int w = pix % WW;
    int h = pix / WW;

    float p1c[LL]; ld8(p1 + pix * LL, p1c);
    float p2c[LL]; ld8(p2 + pix * LL, p2c);

    {
        float uv[LL];  ld8(ui + pix * LL, uv);
        float p3c[LL]; ld8(p3 + pix * LL, p3c);
        float p1u[LL], p2l[LL];
        if (h > 0) {
            ld8(p1 + (pix - WW) * LL, p1u);
        } else {
            #pragma unroll
            for (int z = 0; z < LL; z++) p1u[z] = 0.0f;
        }
        if (w > 0) {
            ld8(p2 + (pix - 1) * LL, p2l);
        } else {
            #pragma unroll
            for (int z = 0; z < LL; z++) p2l[z] = 0.0f;
        }
        float ch = (h < HH - 1) ? 1.0f : 0.0f;
        float cw = (w < WW - 1) ? 1.0f : 0.0f;

        float un[LL], ubv[LL];
        #pragma unroll
        for (int z = 0; z < LL; z++) {
            float d1 = ch * p1c[z] - p1u[z];
            float d2 = cw * p2c[z] - p2l[z];
            float d3 = ((z < LL - 1) ? p3c[z] : 0.0f) - ((z > 0) ? p3c[z - 1] : 0.0f);
            float v  = uv[z] + C_TAUU * (d1 + d2 + d3);
            v = fminf(fmaxf(v, 0.0f), 1.0f);
            un[z]  = v;
            ubv[z] = 2.0f * v - uv[z];
        }
        st8(uo + pix * LL, un);
        if (FULL) st8(ubo + pix * LL, ubv);
    }

    if (FULL) {
        float c1[LL + 1], c2[LL + 1];
        c1[0] = 0.0f; c2[0] = 0.0f;
        #pragma unroll
        for (int z = 0; z < LL; z++) { c1[z + 1] = c1[z] + p1c[z]; c2[z + 1] = c2[z] + p2c[z]; }

        float suf1[LL], suf2[LL];
        float a1 = 0.0f, a2 = 0.0f;
        #pragma unroll
        for (int z = LL - 1; z >= 0; z--) { a1 += c1[z + 1]; a2 += c2[z + 1]; suf1[z] = a1; suf2[z] = a2; }

        float ms[LL], o[LL];
        ld8(msp1 + pix * LL, ms);
        float pr = 0.0f;
        #pragma unroll
        for (int z = 0; z < LL; z++) {
            pr += c1[z];
            float ts = (float)(z + 1) * suf1[z] - (float)(LL - z) * pr;
            o[z] = ms[z] - C_TAUM * ts;
        }
        st8(msn1 + pix * LL, o);

        ld8(msp2 + pix * LL, ms);
        pr = 0.0f;
        #pragma unroll
        for (int z = 0; z < LL; z++) {
            pr += c2[z];
            float ts = (float)(z + 1) * suf2[z] - (float)(LL - z) * pr;
            o[z] = ms[z] - C_TAUM * ts;
        }
        st8(msn2 + pix * LL, o);
    }
}

// =====================================================================
extern "C" void kernel_launch(void* const* d_in, const int* in_sizes, int n_in,
                              void* d_out, int out_size)
{
    const float* u    = (const float*)d_in[0];
    const float* ubar = (const float*)d_in[1];
    const float* p1   = (const float*)d_in[2];
    const float* p2   = (const float*)d_in[3];
    const float* p3   = (const float*)d_in[4];
    const float* s1   = (const float*)d_in[5];
    const float* s2   = (const float*)d_in[6];
    const float* mu1  = (const float*)d_in[7];
    const float* mu2  = (const float*)d_in[8];
    const float* mb1  = (const float*)d_in[9];
    const float* mb2  = (const float*)d_in[10];
    const float* f    = (const float*)d_in[11];
    float* out = (float*)d_out;

    float *gp1, *gp2, *gp3, *gmso1, *gmso2, *gmsp1, *gmsp2, *gmsn1, *gmsn2, *gu, *gub;
    cudaGetSymbolAddress((void**)&gp1,   g_p1);
    cudaGetSymbolAddress((void**)&gp2,   g_p2);
    cudaGetSymbolAddress((void**)&gp3,   g_p3);
    cudaGetSymbolAddress((void**)&gmso1, g_mso1);
    cudaGetSymbolAddress((void**)&gmso2, g_mso2);
    cudaGetSymbolAddress((void**)&gmsp1, g_msp1);
    cudaGetSymbolAddress((void**)&gmsp2, g_msp2);
    cudaGetSymbolAddress((void**)&gmsn1, g_msn1);
    cudaGetSymbolAddress((void**)&gmsn2, g_msn2);
    cudaGetSymbolAddress((void**)&gu,    g_u);
    cudaGetSymbolAddress((void**)&gub,   g_ub);

    dim3 blk(256);
    dim3 grd((NPIX + 255) / 256);
    dim3 cgrd(NPIX / CBLK);

    // all 36-combo streaming isolated here (pipelined, padded transpose)
    kernC<<<cgrd, CBLK>>>(mu1, mu2, s1, s2, mb1, mb2, gmso1, gmso2, gmsp1, gmsp2);

    // iteration 1
    kernA<<<grd, blk>>>(ubar, p1, p2, p3, gmso1, gmso2, f, gp1, gp2, gp3);
    kernB<true><<<grd, blk>>>(u, gp1, gp2, gp3, gmsp1, gmsp2, gu, gub, gmsn1, gmsn2);

    // iteration 2 (l2proj & mu dead w.r.t. returned u)
    kernA<<<grd, blk>>>(gub, gp1, gp2, gp3, gmsn1, gmsn2, f, gp1, gp2, gp3);
    kernB<false><<<grd, blk>>>(gu, gp1, gp2, gp3, gmsp1, gmsp2, out, gub, gmsn1, gmsn2);
}

// round 15
// speedup vs baseline: 1.4037x; 1.4037x over previous
#include <cuda_runtime.h>
#include <math.h>

#define HH 768
#define WW 768
#define LL 8
#define PP 36
#define NPIX (HH*WW)
#define CBLK 128
#define CPAD 37

#define C_SIGMAP (1.0f / 11.0f)   /* 1/(3+L) */
#define C_LMBDA  0.1f
#define C_NU     0.01f
#define C_TAUU   (1.0f / 6.0f)
#define C_TAUM   (1.0f / 11.0f)   /* 1/(2+PROJ/4) */

// ---- scratch (allocation-free rule: device globals) ----
__device__ float g_p1[NPIX * LL];
__device__ float g_p2[NPIX * LL];
__device__ float g_p3[NPIX * LL];
__device__ float g_mso1[NPIX * LL];   // level-sums of INPUT mu   (kernC -> kernA iter1)
__device__ float g_mso2[NPIX * LL];
__device__ float g_msp1[NPIX * LL];   // mso + tau*levelsum(proj s) (kernC -> kernA iter2)
__device__ float g_msp2[NPIX * LL];
__device__ float g_u [NPIX * LL];
__device__ float g_ub[NPIX * LL];

// K -> (k1,k2) for the upper-triangular combo ordering (k1 outer, k2 inner)
__device__ __host__ constexpr int kk1(int K) {
    int k1 = 0, r = K, c = LL;
    while (r >= c) { r -= c; k1++; c--; }
    return k1;
}
__device__ __host__ constexpr int kk2(int K) {
    int k1 = 0, r = K, c = LL;
    while (r >= c) { r -= c; k1++; c--; }
    return k1 + r;
}

__device__ __forceinline__ void ld8(const float* __restrict__ p, float* v) {
    float4 a = *(const float4*)p;
    float4 b = *(const float4*)(p + 4);
    v[0]=a.x; v[1]=a.y; v[2]=a.z; v[3]=a.w;
    v[4]=b.x; v[5]=b.y; v[6]=b.z; v[7]=b.w;
}
__device__ __forceinline__ void st8(float* __restrict__ p, const float* v) {
    *(float4*)p       = make_float4(v[0], v[1], v[2], v[3]);
    *(float4*)(p + 4) = make_float4(v[4], v[5], v[6], v[7]);
}

// =====================================================================
// Kernel C: PP-field streaming via padded smem transpose (exact R7
// best-measured form: scalar __ldcs staging, stride-37 scalar reads).
// Emits: mso = level-sums of input mu
//        msp = mso + tau * level-sums(proj(s - mb))
// =====================================================================
__global__ __launch_bounds__(CBLK)
void kernC(const float* __restrict__ mu1i, const float* __restrict__ mu2i,
           const float* __restrict__ s1i,  const float* __restrict__ s2i,
           const float* __restrict__ mb1i, const float* __restrict__ mb2i,
           float* __restrict__ mso1, float* __restrict__ mso2,
           float* __restrict__ msp1, float* __restrict__ msp2)
{
    __shared__ float bufA[CBLK * CPAD];
    __shared__ float bufB[CBLK * CPAD];

    const int tid = threadIdx.x;
    const int pix = blockIdx.x * CBLK + tid;
    const size_t base = (size_t)blockIdx.x * CBLK * PP;

    // ---- phase 1: stage mu1 / mu2 (coalesced), reduce to level sums ----
    #pragma unroll
    for (int j = 0; j < PP; j++) {
        int flat = j * CBLK + tid;
        int r = flat / PP, c = flat % PP;
        bufA[r * CPAD + c] = __ldcs(mu1i + base + flat);
        bufB[r * CPAD + c] = __ldcs(mu2i + base + flat);
    }
    __syncthreads();

    float ms1[LL], ms2[LL];
    {
        float d1[LL + 1], d2[LL + 1];
        #pragma unroll
        for (int z = 0; z <= LL; z++) { d1[z] = 0.0f; d2[z] = 0.0f; }
        const float* rowA = bufA + tid * CPAD;
        const float* rowB = bufB + tid * CPAD;
        #pragma unroll
        for (int K = 0; K < PP; K++) {
            float v1 = rowA[K];
            float v2 = rowB[K];
            d1[kk1(K)] += v1;  d1[kk2(K) + 1] -= v1;
            d2[kk1(K)] += v2;  d2[kk2(K) + 1] -= v2;
        }
        float a1 = 0.0f, a2 = 0.0f;
        #pragma unroll
        for (int z = 0; z < LL; z++) { a1 += d1[z]; a2 += d2[z]; ms1[z] = a1; ms2[z] = a2; }
    }
    st8(mso1 + pix * LL, ms1);
    st8(mso2 + pix * LL, ms2);
    __syncthreads();   // before buffer reuse

    // ---- phase 2: stage a = s - mb (coalesced), project + reduce ----
    #pragma unroll
    for (int j = 0; j < PP; j++) {
        int flat = j * CBLK + tid;
        int r = flat / PP, c = flat % PP;
        bufA[r * CPAD + c] = __ldcs(s1i + base + flat) - __ldcs(mb1i + base + flat);
        bufB[r * CPAD + c] = __ldcs(s2i + base + flat) - __ldcs(mb2i + base + flat);
    }
    __syncthreads();

    {
        float d1[LL + 1], d2[LL + 1];
        #pragma unroll
        for (int z = 0; z <= LL; z++) { d1[z] = 0.0f; d2[z] = 0.0f; }
        const float* rowA = bufA + tid * CPAD;
        const float* rowB = bufB + tid * CPAD;
        #pragma unroll
        for (int K = 0; K < PP; K++) {
            float a1 = rowA[K];
            float a2 = rowB[K];
            float nr = sqrtf(a1 * a1 + a2 * a2);
            if (nr > C_NU) { float rr = __fdividef(C_NU, nr); a1 *= rr; a2 *= rr; }
            d1[kk1(K)] += a1;  d1[kk2(K) + 1] -= a1;
            d2[kk1(K)] += a2;  d2[kk2(K) + 1] -= a2;
        }
        float a1 = 0.0f, a2 = 0.0f;
        float o1[LL], o2[LL];
        #pragma unroll
        for (int z = 0; z < LL; z++) {
            a1 += d1[z]; a2 += d2[z];
            o1[z] = ms1[z] + C_TAUM * a1;
            o2[z] = ms2[z] + C_TAUM * a2;
        }
        st8(msp1 + pix * LL, o1);
        st8(msp2 + pix * LL, o2);
    }
}

// =====================================================================
// Kernel A: parabola projection.
// MSN=false (iter1): ms inputs are the level-sums directly (mso).
// MSN=true  (iter2): ms inputs are msp; the updated-mu level sums are
//   reconstructed in registers: ms[z] = msp[z] - tau * TS[z], with
//   TS from the prefix/suffix sums of the p rows ALREADY loaded here.
//   (Identical arithmetic to the old kernB msn path; kills the msn
//   gmem round-trip entirely.)
// =====================================================================
template <bool MSN>
__global__ __launch_bounds__(256)
void kernA(const float* __restrict__ ubar,
           const float* __restrict__ p1i, const float* __restrict__ p2i, const float* __restrict__ p3i,
           const float* __restrict__ ms1i, const float* __restrict__ ms2i,
           const float* __restrict__ f,
           float* __restrict__ p1o, float* __restrict__ p2o, float* __restrict__ p3o)
{
    int pix = blockIdx.x * blockDim.x + threadIdx.x;
    if (pix >= NPIX) return;
    int w = pix % WW;
    int h = pix / WW;

    // ---- forward differences of ubar ----
    float U1[LL], U2[LL], U3[LL];
    {
        float ub[LL];
        ld8(ubar + pix * LL, ub);
        if (h < HH - 1) {
            float nb[LL]; ld8(ubar + (pix + WW) * LL, nb);
            #pragma unroll
            for (int z = 0; z < LL; z++) U1[z] = nb[z] - ub[z];
        } else {
            #pragma unroll
            for (int z = 0; z < LL; z++) U1[z] = 0.0f;
        }
        if (w < WW - 1) {
            float nb[LL]; ld8(ubar + (pix + 1) * LL, nb);
            #pragma unroll
            for (int z = 0; z < LL; z++) U2[z] = nb[z] - ub[z];
        } else {
            #pragma unroll
            for (int z = 0; z < LL; z++) U2[z] = 0.0f;
        }
        #pragma unroll
        for (int z = 0; z < LL; z++) U3[z] = (z < LL - 1) ? (ub[z + 1] - ub[z]) : 0.0f;
    }

    // ---- fold p + sigmap*(diff + ms) into U; ms maybe reconstructed ----
    {
        float ms[LL], pv[LL];

        ld8(p1i + pix * LL, pv);
        ld8(ms1i + pix * LL, ms);
        if (MSN) {
            float c[LL + 1];
            c[0] = 0.0f;
            #pragma unroll
            for (int z = 0; z < LL; z++) c[z + 1] = c[z] + pv[z];
            float suf[LL];
            float a = 0.0f;
            #pragma unroll
            for (int z = LL - 1; z >= 0; z--) { a += c[z + 1]; suf[z] = a; }
            float pr = 0.0f;
            #pragma unroll
            for (int z = 0; z < LL; z++) {
                pr += c[z];
                float ts = (float)(z + 1) * suf[z] - (float)(LL - z) * pr;
                ms[z] = ms[z] - C_TAUM * ts;
            }
        }
        #pragma unroll
        for (int z = 0; z < LL; z++) U1[z] = pv[z] + C_SIGMAP * (U1[z] + ms[z]);

        ld8(p2i + pix * LL, pv);
        ld8(ms2i + pix * LL, ms);
        if (MSN) {
            float c[LL + 1];
            c[0] = 0.0f;
            #pragma unroll
            for (int z = 0; z < LL; z++) c[z + 1] = c[z] + pv[z];
            float suf[LL];
            float a = 0.0f;
            #pragma unroll
            for (int z = LL - 1; z >= 0; z--) { a += c[z + 1]; suf[z] = a; }
            float pr = 0.0f;
            #pragma unroll
            for (int z = 0; z < LL; z++) {
                pr += c[z];
                float ts = (float)(z + 1) * suf[z] - (float)(LL - z) * pr;
                ms[z] = ms[z] - C_TAUM * ts;
            }
        }
        #pragma unroll
        for (int z = 0; z < LL; z++) U2[z] = pv[z] + C_SIGMAP * (U2[z] + ms[z]);

        ld8(p3i + pix * LL, pv);
        #pragma unroll
        for (int z = 0; z < LL; z++) U3[z] = pv[z] + C_SIGMAP * U3[z];
    }

    float fv = __ldg(f + pix);

    // ---- cubic parabola projection, results overwrite U in place ----
    #pragma unroll
    for (int z = 0; z < LL; z++) {
        float t    = (float)(z + 1) * (1.0f / (float)LL) - fv;
        float quad = C_LMBDA * t * t;
        float n2   = U1[z] * U1[z] + U2[z] * U2[z];
        float B    = 0.25f * n2 - quad;
        if (U3[z] < B) {
            float y   = U3[z] + quad;
            float nrm = sqrtf(n2);
            float a   = 0.5f * nrm;
            float b   = (2.0f / 3.0f) * (1.0f - 0.5f * y);
            float sb  = sqrtf(fmaxf(-b, 0.0f));
            float sb3 = sb * sb * sb;
            float d   = (b < 0.0f) ? (a - sb3) * (a + sb3) : fmaf(b * b, b, a * a);
            float v;
            if (d < 0.0f) {
                float ca = fminf(fmaxf(__fdividef(a, sb3), -1.0f), 1.0f);
                v = 2.0f * sb * __cosf(acosf(ca) * (1.0f / 3.0f));
            } else {
                float x  = a + sqrtf(d);
                float c  = (x > 0.0f) ? __powf(x, 1.0f / 3.0f) : 0.0f;
                v = (c == 0.0f) ? 0.0f : (c - __fdividef(b, c));
            }
            float r1, r2;
            if (nrm == 0.0f) { r1 = 0.0f; r2 = 0.0f; }
            else {
                float s = __fdividef(2.0f * v, nrm);
                r1 = s * U1[z]; r2 = s * U2[z];
            }
            U1[z] = r1;
            U2[z] = r2;
            U3[z] = 0.25f * (r1 * r1 + r2 * r2) - quad;
        }
    }
    st8(p1o + pix * LL, U1);
    st8(p2o + pix * LL, U2);
    st8(p3o + pix * LL, U3);
}

// =====================================================================
// Kernel B: clipping only (divergence + clamp + over-relaxation).
// =====================================================================
template <bool WRITE_UBAR>
__global__ __launch_bounds__(256)
void kernB(const float* __restrict__ ui,
           const float* __restrict__ p1, const float* __restrict__ p2, const float* __restrict__ p3,
           float* __restrict__ uo, float* __restrict__ ubo)
{
    int pix = blockIdx.x * blockDim.x + threadIdx.x;
    if (pix >= NPIX) return;
    int w = pix % WW;
    int h = pix / WW;

    float uv[LL];  ld8(ui + pix * LL, uv);
    float p1c[LL]; ld8(p1 + pix * LL, p1c);
    float p2c[LL]; ld8(p2 + pix * LL, p2c);
    float p3c[LL]; ld8(p3 + pix * LL, p3c);

    float p1u[LL], p2l[LL];
    if (h > 0) {
        ld8(p1 + (pix - WW) * LL, p1u);
    } else {
        #pragma unroll
        for (int z = 0; z < LL; z++) p1u[z] = 0.0f;
    }
    if (w > 0) {
        ld8(p2 + (pix - 1) * LL, p2l);
    } else {
        #pragma unroll
        for (int z = 0; z < LL; z++) p2l[z] = 0.0f;
    }

    float ch = (h < HH - 1) ? 1.0f : 0.0f;
    float cw = (w < WW - 1) ? 1.0f : 0.0f;

    float un[LL], ubv[LL];
    #pragma unroll
    for (int z = 0; z < LL; z++) {
        float d1 = ch * p1c[z] - p1u[z];
        float d2 = cw * p2c[z] - p2l[z];
        float d3 = ((z < LL - 1) ? p3c[z] : 0.0f) - ((z > 0) ? p3c[z - 1] : 0.0f);
        float v  = uv[z] + C_TAUU * (d1 + d2 + d3);
        v = fminf(fmaxf(v, 0.0f), 1.0f);
        un[z]  = v;
        ubv[z] = 2.0f * v - uv[z];
    }
    st8(uo + pix * LL, un);
    if (WRITE_UBAR) st8(ubo + pix * LL, ubv);
}

// =====================================================================
extern "C" void kernel_launch(void* const* d_in, const int* in_sizes, int n_in,
                              void* d_out, int out_size)
{
    const float* u    = (const float*)d_in[0];
    const float* ubar = (const float*)d_in[1];
    const float* p1   = (const float*)d_in[2];
    const float* p2   = (const float*)d_in[3];
    const float* p3   = (const float*)d_in[4];
    const float* s1   = (const float*)d_in[5];
    const float* s2   = (const float*)d_in[6];
    const float* mu1  = (const float*)d_in[7];
    const float* mu2  = (const float*)d_in[8];
    const float* mb1  = (const float*)d_in[9];
    const float* mb2  = (const float*)d_in[10];
    const float* f    = (const float*)d_in[11];
    float* out = (float*)d_out;

    float *gp1, *gp2, *gp3, *gmso1, *gmso2, *gmsp1, *gmsp2, *gu, *gub;
    cudaGetSymbolAddress((void**)&gp1,   g_p1);
    cudaGetSymbolAddress((void**)&gp2,   g_p2);
    cudaGetSymbolAddress((void**)&gp3,   g_p3);
    cudaGetSymbolAddress((void**)&gmso1, g_mso1);
    cudaGetSymbolAddress((void**)&gmso2, g_mso2);
    cudaGetSymbolAddress((void**)&gmsp1, g_msp1);
    cudaGetSymbolAddress((void**)&gmsp2, g_msp2);
    cudaGetSymbolAddress((void**)&gu,    g_u);
    cudaGetSymbolAddress((void**)&gub,   g_ub);

    dim3 blk(256);
    dim3 grd((NPIX + 255) / 256);
    dim3 cgrd(NPIX / CBLK);

    // all 36-combo streaming isolated here (R7 best-known form)
    kernC<<<cgrd, CBLK>>>(mu1, mu2, s1, s2, mb1, mb2, gmso1, gmso2, gmsp1, gmsp2);

    // iteration 1
    kernA<false><<<grd, blk>>>(ubar, p1, p2, p3, gmso1, gmso2, f, gp1, gp2, gp3);
    kernB<true><<<grd, blk>>>(u, gp1, gp2, gp3, gu, gub);

    // iteration 2: msn reconstructed in-register from msp + p rows
    kernA<true><<<grd, blk>>>(gub, gp1, gp2, gp3, gmsp1, gmsp2, f, gp1, gp2, gp3);
    kernB<false><<<grd, blk>>>(gu, gp1, gp2, gp3, out, gub);
}